// round 11
// baseline (speedup 1.0000x reference)
#include <cuda_runtime.h>
#include <cstdint>
#include <math.h>

// Problem constants
#define HH 512
#define BB 64
#define NN 2048
#define NF 256

constexpr int KT = 256;          // k-tile per block
constexpr int JC = 8;            // j chunk
constexpr int NCHUNK = HH / JC;  // 64

// 1/sqrt(512) — the reference's compat normalization (fp32)
#define NORM_F 0.04419417382f

// ---------------- device scratch (static, no allocation) ----------------
__device__ float g_xT[HH * BB];                       // x transposed [j][b]
__device__ float g_partQ[(size_t)HH * BB * HH];       // 67 MB: [h][b][k]
__device__ float g_Q[BB * HH];                        // [b][k]
__device__ float g_partU[2 * BB * HH];                // [kh][b][h]
__device__ float g_compat[BB * NN];
__device__ int   g_top[BB * NF];

// ---------------- f32x2 helpers ----------------
__device__ __forceinline__ unsigned long long pack2(float lo, float hi) {
    unsigned long long r;
    asm("mov.b64 %0, {%1, %2};" : "=l"(r) : "f"(lo), "f"(hi));
    return r;
}
__device__ __forceinline__ void unpack2(unsigned long long v, float& lo, float& hi) {
    asm("mov.b64 {%0, %1}, %2;" : "=f"(lo), "=f"(hi) : "l"(v));
}
__device__ __forceinline__ void fma2(unsigned long long& d, unsigned long long a,
                                     unsigned long long b) {
    asm("fma.rn.f32x2 %0, %1, %2, %0;" : "+l"(d) : "l"(a), "l"(b));
}
__device__ __forceinline__ unsigned long long add2(unsigned long long a,
                                                   unsigned long long b) {
    unsigned long long r;
    asm("add.rn.f32x2 %0, %1, %2;" : "=l"(r) : "l"(a), "l"(b));
    return r;
}
__device__ __forceinline__ unsigned long long mul2(unsigned long long a,
                                                   unsigned long long b) {
    unsigned long long r;
    asm("mul.rn.f32x2 %0, %1, %2;" : "=l"(r) : "l"(a), "l"(b));
    return r;
}

// ---------------- prep: transpose x ----------------
__global__ void prep_kernel(const float* __restrict__ vs) {
    int idx = blockIdx.x * 256 + threadIdx.x;
    if (idx < HH * BB) {
        int j = idx >> 6;
        int b = idx & 63;
        g_xT[idx] = vs[b * HH + j];  // vs[b,0,j]
    }
}

// ---------------- fused generation GEMM + contraction (f32x2) ----------------
// gemm[b,h,k] = sum_j x[b,j] * W[j, h*512+k]   (h = blockIdx.x, k-tile = blockIdx.y)
// MODE 0: partQ[h][b][k]  = x[b,h] * (gemm[b,h,k] + bias[h,k])
// MODE 1: partU[kh][b][h] = sum_k  (gemm[b,h,k] + bias[h,k]) * Q[b,k]
template <int MODE>
__global__ void __launch_bounds__(256, 2)
gen_kernel(const float* __restrict__ W, const float* __restrict__ bias) {
    const int h  = blockIdx.x;
    const int kh = blockIdx.y;
    const int kb = kh * KT;

    __shared__ __align__(16) float sW[2][JC][KT];        // 16 KB, pair-permuted
    __shared__ __align__(16) float sX[2][JC][BB * 2];    // 8 KB, duplicated pairs
    __shared__ double sRed[BB][17];                      // 8.7 KB

    const int tid = threadIdx.x;
    const int tx = tid & 15;   // covers k = tx + 32q (lo) and tx + 16 + 32q (hi)
    const int ty = tid >> 4;   // b = ty*4 + i

    unsigned long long acc[4][8];
#pragma unroll
    for (int i = 0; i < 4; i++)
#pragma unroll
        for (int q = 0; q < 8; q++) acc[i][q] = 0ULL;

    const size_t wcol = (size_t)h * HH + kb;

    auto load_chunk = [&](int c, int buf) {
        const int j0 = c * JC;
        // W chunk pair-permuted: float offset for logical k:
        // ((k>>5)<<5) | ((k&15)<<1) | ((k>>4)&1)
#pragma unroll
        for (int t = 0; t < 2; t++) {
            int i = tid + t * 256;          // 0..511 float4 ids
            int r = i >> 6;                 // row (0..7)
            int c4 = i & 63;
            float4 v = *(const float4*)(W + (size_t)(j0 + r) * (HH * HH) + wcol + (c4 << 2));
            int k0 = c4 << 2;
#pragma unroll
            for (int e = 0; e < 4; e++) {
                int k = k0 + e;
                int off = ((k >> 5) << 5) | ((k & 15) << 1) | ((k >> 4) & 1);
                sW[buf][r][off] = (&v.x)[e];
            }
        }
#pragma unroll
        for (int t = 0; t < 2; t++) {
            int i = tid + t * 256;          // 0..511
            int r = i >> 6;
            int b = i & 63;
            float xv = g_xT[(j0 + r) * BB + b];
            sX[buf][r][2 * b]     = xv;
            sX[buf][r][2 * b + 1] = xv;
        }
    };

    load_chunk(0, 0);
    __syncthreads();
    int buf = 0;
    for (int c = 0; c < NCHUNK; c++) {
        if (c + 1 < NCHUNK) load_chunk(c + 1, buf ^ 1);
#pragma unroll
        for (int jj = 0; jj < JC; jj++) {
            unsigned long long wv[8];
            const unsigned long long* wp =
                (const unsigned long long*)(&sW[buf][jj][0]) + tx;
#pragma unroll
            for (int q = 0; q < 8; q++) wv[q] = wp[q * 16];
            const ulonglong2* xp =
                (const ulonglong2*)(&sX[buf][jj][0]) + (ty << 1);
            ulonglong2 x01 = xp[0];
            ulonglong2 x23 = xp[1];
            unsigned long long xv[4] = {x01.x, x01.y, x23.x, x23.y};
#pragma unroll
            for (int i = 0; i < 4; i++)
#pragma unroll
                for (int q = 0; q < 8; q++) fma2(acc[i][q], xv[i], wv[q]);
        }
        __syncthreads();
        buf ^= 1;
    }

    unsigned long long bv[8];
#pragma unroll
    for (int q = 0; q < 8; q++) {
        float blo = bias[wcol + tx + 32 * q];
        float bhi = bias[wcol + tx + 32 * q + 16];
        bv[q] = pack2(blo, bhi);
    }

    if (MODE == 0) {
#pragma unroll
        for (int i = 0; i < 4; i++) {
            int b = ty * 4 + i;
            float xh = g_xT[h * BB + b];
            unsigned long long xh2 = pack2(xh, xh);
            float* dst = g_partQ + (size_t)h * (BB * HH) + b * HH + kb;
#pragma unroll
            for (int q = 0; q < 8; q++) {
                unsigned long long ct = add2(acc[i][q], bv[q]);
                unsigned long long pr = mul2(ct, xh2);
                float lo, hi;
                unpack2(pr, lo, hi);
                dst[tx + 32 * q]      = lo;
                dst[tx + 32 * q + 16] = hi;
            }
        }
    } else {
        double part[4] = {0.0, 0.0, 0.0, 0.0};
#pragma unroll
        for (int i = 0; i < 4; i++) {
            int b = ty * 4 + i;
            const float* qrow = g_Q + b * HH + kb;
#pragma unroll
            for (int q = 0; q < 8; q++) {
                unsigned long long ct = add2(acc[i][q], bv[q]);
                float lo, hi;
                unpack2(ct, lo, hi);
                part[i] += (double)lo * (double)qrow[tx + 32 * q] +
                           (double)hi * (double)qrow[tx + 32 * q + 16];
            }
        }
#pragma unroll
        for (int i = 0; i < 4; i++) sRed[ty * 4 + i][tx] = part[i];
        __syncthreads();
        if (tid < BB) {
            double s = 0.0;
#pragma unroll
            for (int t = 0; t < 16; t++) s += sRed[tid][t];  // fixed order
            g_partU[(kh * BB + tid) * HH + h] = (float)s;
        }
    }
}

// ---------------- deterministic reduction of partQ over h ----------------
__global__ void reduceQ_kernel() {
    int idx = blockIdx.x * 256 + threadIdx.x;  // b*512 + k
    double s = 0.0;
    for (int h = 0; h < HH; h++) s += (double)g_partQ[(size_t)h * (BB * HH) + idx];
    g_Q[idx] = (float)s;
}

// ---------------- compat[b,n] = norm * ( ve[b,n,:] . u[b,:] ) ----------------
__global__ void compat_kernel(const float* __restrict__ ve) {
    int b = blockIdx.y;
    __shared__ float su[HH];
    for (int i = threadIdx.x; i < HH; i += 256)
        su[i] = g_partU[b * HH + i] + g_partU[(BB + b) * HH + i];
    __syncthreads();

    int warp = threadIdx.x >> 5, lane = threadIdx.x & 31;
    for (int r = warp; r < 64; r += 8) {
        int n = blockIdx.x * 64 + r;
        const float4* row = (const float4*)(ve + ((size_t)b * NN + n) * HH);
        const float4* uu = (const float4*)su;
        double s = 0.0;
#pragma unroll
        for (int c4 = lane; c4 < 128; c4 += 32) {
            float4 v = row[c4];
            float4 w = uu[c4];
            s += (double)v.x * w.x + (double)v.y * w.y +
                 (double)v.z * w.z + (double)v.w * w.w;
        }
#pragma unroll
        for (int o = 16; o; o >>= 1) s += __shfl_xor_sync(0xffffffffu, s, o);
        if (lane == 0)
            g_compat[b * NN + n] = __fmul_rn((float)s, NORM_F);  // fp32 scale, as reference
    }
}

// ---------------- reference expf replica: cephes core + FLUSH BELOW FLT_MIN ----
// Round-9 evidence: 63/64 batches matched with the cephes zero-at-(fx<=-127)
// cutoff; the one failure was an fp32-SUBNORMAL exp result (fx=-126, y<1) that
// the reference treats as 0. => reference zeroes any result < 2^-126 (FLT_MIN):
// effective cutoff d < -126*ln2 = -87.33654. Normal-range results are exact RN32.
__device__ double exp_ref_f32(float din) {
    float cx = fminf(din, 88.3762626647950f);
    cx = fmaxf(cx, -88.3762626647949f);
    float fx = floorf(__fadd_rn(__fmul_rn(cx, 1.44269504088896341f), 0.5f));
    if (fx <= -127.0f) return 0.0;
    float tmp = __fmul_rn(fx, 0.693359375f);
    float zz  = __fmul_rn(fx, -2.12194440e-4f);
    float x = __fsub_rn(cx, tmp);
    x = __fsub_rn(x, zz);
    float z = __fmul_rn(x, x);
    float y = 1.9875691500e-4f;
    y = __fmaf_rn(y, x, 1.3981999507e-3f);
    y = __fmaf_rn(y, x, 8.3334519073e-3f);
    y = __fmaf_rn(y, x, 4.1665795894e-2f);
    y = __fmaf_rn(y, x, 1.6666665459e-1f);
    y = __fmaf_rn(y, x, 5.0000001201e-1f);
    y = __fmaf_rn(y, z, x);
    y = __fadd_rn(y, 1.0f);
    int n = (int)fx;                        // n in [-126, 127]
    double e = ldexp((double)y, n);         // exact in double
    if (e < 1.1754943508222875e-38) return 0.0;   // subnormal result -> flushed
    return (double)(float)e;                // normal range: exact RN32
}

// ---------------- top-256 replicating fp32 softmax + stable argsort ------------
// score = RN32( exp32(compat - max) / RN32(sum) ); all entries whose exp flushed
// to zero form one tie group ordered by ascending index (stable argsort of
// -score). Exact O(N^2) rank-count on (score desc, index asc).
__global__ void __launch_bounds__(512)
topk_kernel() {
    int b = blockIdx.x;
    __shared__ float sv[NN];               // 8 KB
    __shared__ double se[NN];              // 16 KB, reused for keys
    __shared__ float smax[512];            // 2 KB
    __shared__ double ssum[512];           // 4 KB
    int tid = threadIdx.x;

    float lm = -3.0e38f;
    for (int i = tid; i < NN; i += 512) {
        float v = g_compat[b * NN + i];
        sv[i] = v;
        lm = fmaxf(lm, v);
    }
    smax[tid] = lm;
    __syncthreads();
    for (int s = 256; s; s >>= 1) {
        if (tid < s) smax[tid] = fmaxf(smax[tid], smax[tid + s]);
        __syncthreads();
    }
    float m = smax[0];

    double ls = 0.0;
    for (int i = tid; i < NN; i += 512) {
        double e = exp_ref_f32(__fsub_rn(sv[i], m));
        se[i] = e;
        ls += e;
    }
    ssum[tid] = ls;
    __syncthreads();
    for (int s = 256; s; s >>= 1) {
        if (tid < s) ssum[tid] += ssum[tid + s];   // fixed-order: deterministic
        __syncthreads();
    }
    float ssf = (float)ssum[0];

    unsigned long long* keys = (unsigned long long*)se;  // in-place reuse
    for (int i = tid; i < NN; i += 512) {
        double t = se[i] / (double)ssf;    // exact quotient; RN32 below = fp32 div
        unsigned u;
        if (t >= 1.1754943508222875e-38) {
            u = __float_as_uint((float)t);                     // normal: exact RN32
        } else {
            u = (unsigned)(long long)nearbyint(t * 0x1p+149);  // subnormal bits / 0
        }
        keys[i] = ((unsigned long long)u << 32) | (unsigned)(NN - 1 - i);
    }
    __syncthreads();

#pragma unroll
    for (int tt = 0; tt < 4; tt++) {
        int i = tt * 512 + tid;
        unsigned long long me = keys[i];
        int cnt = 0;
#pragma unroll 8
        for (int j = 0; j < NN; j++) cnt += (keys[j] > me) ? 1 : 0;
        if (cnt < NF) g_top[b * NF + cnt] = i;
    }
}

// ---------------- gather ----------------
__global__ void gather_kernel(const float* __restrict__ ve, float* __restrict__ out) {
    int b = blockIdx.y, r = blockIdx.x;
    int src = g_top[b * NF + r];
    const float4* s = (const float4*)(ve + ((size_t)b * NN + src) * HH);
    float4* d = (float4*)(out + ((size_t)b * NF + r) * HH);
    d[threadIdx.x] = s[threadIdx.x];
}

// ---------------- launch ----------------
extern "C" void kernel_launch(void* const* d_in, const int* in_sizes, int n_in,
                              void* d_out, int out_size) {
    // Identify inputs by element count (robust, keeps relative order of pairs):
    // vs=32768, ve=67108864, Wq/Wk=134217728, bq/bk=262144.
    const float* vs = nullptr;
    const float* ve = nullptr;
    const float* Wq = nullptr;
    const float* Wk = nullptr;
    const float* bq = nullptr;
    const float* bk = nullptr;
    int nW = 0, nB = 0;
    for (int i = 0; i < n_in; i++) {
        const float* p = (const float*)d_in[i];
        int s = in_sizes[i];
        if (s == 32768) vs = p;
        else if (s == 67108864) ve = p;
        else if (s == 134217728) { if (nW++ == 0) Wq = p; else Wk = p; }
        else if (s == 262144)    { if (nB++ == 0) bq = p; else bk = p; }
    }
    float* out = (float*)d_out;

    prep_kernel<<<128, 256>>>(vs);
    gen_kernel<0><<<dim3(HH, 2), 256>>>(Wq, bq);
    reduceQ_kernel<<<128, 256>>>();
    gen_kernel<1><<<dim3(HH, 2), 256>>>(Wk, bk);
    compat_kernel<<<dim3(32, BB), 256>>>(ve);
    topk_kernel<<<BB, 512>>>();
    gather_kernel<<<dim3(NF, BB), 128>>>(ve, out);
}

// round 16
// speedup vs baseline: 1.2234x; 1.2234x over previous
#include <cuda_runtime.h>
#include <cstdint>
#include <math.h>

// Problem constants
#define HH 512
#define BB 64
#define NN 2048
#define NF 256

constexpr int KT = 256;          // k-tile per block (128 f32x2 pairs)
constexpr int JC = 8;            // j chunk
constexpr int NCHUNK = HH / JC;  // 64

// 1/sqrt(512) — the reference's compat normalization (fp32)
#define NORM_F 0.04419417382f

// ---------------- device scratch (static, no allocation) ----------------
__device__ float g_xT[HH * BB];                       // x transposed [j][b]
__device__ float g_partQ[(size_t)HH * BB * HH];       // 67 MB: [h][b][k]
__device__ float g_Q[BB * HH];                        // [b][k]
__device__ float g_partU[2 * BB * HH];                // [kh][b][h]
__device__ float g_compat[BB * NN];
__device__ int   g_top[BB * NF];

// ---------------- f32x2 helpers ----------------
__device__ __forceinline__ unsigned long long pack2(float lo, float hi) {
    unsigned long long r;
    asm("mov.b64 %0, {%1, %2};" : "=l"(r) : "f"(lo), "f"(hi));
    return r;
}
__device__ __forceinline__ void unpack2(unsigned long long v, float& lo, float& hi) {
    asm("mov.b64 {%0, %1}, %2;" : "=f"(lo), "=f"(hi) : "l"(v));
}
__device__ __forceinline__ void fma2(unsigned long long& d, unsigned long long a,
                                     unsigned long long b) {
    asm("fma.rn.f32x2 %0, %1, %2, %0;" : "+l"(d) : "l"(a), "l"(b));
}
__device__ __forceinline__ unsigned long long add2(unsigned long long a,
                                                   unsigned long long b) {
    unsigned long long r;
    asm("add.rn.f32x2 %0, %1, %2;" : "=l"(r) : "l"(a), "l"(b));
    return r;
}
__device__ __forceinline__ unsigned long long mul2(unsigned long long a,
                                                   unsigned long long b) {
    unsigned long long r;
    asm("mul.rn.f32x2 %0, %1, %2;" : "=l"(r) : "l"(a), "l"(b));
    return r;
}

// ---------------- prep: transpose x ----------------
__global__ void prep_kernel(const float* __restrict__ vs) {
    int idx = blockIdx.x * 256 + threadIdx.x;
    if (idx < HH * BB) {
        int j = idx >> 6;
        int b = idx & 63;
        g_xT[idx] = vs[b * HH + j];  // vs[b,0,j]
    }
}

// ---------------- fused generation GEMM + contraction (f32x2, pipelined) -----
// gemm[b,h,k] = sum_j x[b,j] * W[j, h*512+k]   (h = blockIdx.x, k-tile = blockIdx.y)
// MODE 0: partQ[h][b][k]  = x[b,h] * (gemm[b,h,k] + bias[h,k])
// MODE 1: partU[kh][b][h] = sum_k  (gemm[b,h,k] + bias[h,k]) * Q[b,k]
//
// Pipeline: LDG chunk c+1 into REGISTERS at loop top, FFMA2 on chunk c from
// smem, STS the registers AFTER the compute, barrier. DRAM latency (~600cy)
// hides under ~2000cy of compute per chunk per SMSP.
// Pairs are ADJACENT floats (k = 2p, 2p+1): natural layouts, vector LDS/STS,
// float2 bias/Q/output. Thread covers pairs p = tx + 16q, q<8; b = ty*4+i.
template <int MODE>
__global__ void __launch_bounds__(256, 2)
gen_kernel(const float* __restrict__ W, const float* __restrict__ bias) {
    const int h  = blockIdx.x;
    const int kh = blockIdx.y;
    const int kb = kh * KT;

    __shared__ __align__(16) float sW[2][JC][KT];   // 16 KB
    __shared__ __align__(16) float sX[2][JC][BB];   // 4 KB
    __shared__ double sRed[BB][17];                 // 8.7 KB (MODE 1 only)

    const int tid = threadIdx.x;
    const int tx = tid & 15;
    const int ty = tid >> 4;

    // W-load mapping: float4 id i = tid + t*256 (t<2); row r = i>>6, col4 = i&63
    const int r0 = tid >> 6;           // t=0 row (0..3)
    const int c4 = tid & 63;           // float4 column
    // x-load mapping: element i = tid + t*256; row i>>6, b = i&63

    unsigned long long acc[4][8];
#pragma unroll
    for (int i = 0; i < 4; i++)
#pragma unroll
        for (int q = 0; q < 8; q++) acc[i][q] = 0ULL;

    const size_t wcol = (size_t)h * HH + kb;

    float4 wreg0, wreg1;
    float  xreg0, xreg1;

    auto prefetch = [&](int c) {
        const int j0 = c * JC;
        wreg0 = *(const float4*)(W + (size_t)(j0 + r0)     * (HH * HH) + wcol + (c4 << 2));
        wreg1 = *(const float4*)(W + (size_t)(j0 + r0 + 4) * (HH * HH) + wcol + (c4 << 2));
        xreg0 = g_xT[(j0 + r0)     * BB + c4];   // (i>>6, i&63) with i=tid
        xreg1 = g_xT[(j0 + r0 + 4) * BB + c4];   // i = tid + 256
    };
    auto commit = [&](int buf) {
        *(float4*)(&sW[buf][r0][c4 << 2])     = wreg0;
        *(float4*)(&sW[buf][r0 + 4][c4 << 2]) = wreg1;
        sX[buf][r0][c4]     = xreg0;
        sX[buf][r0 + 4][c4] = xreg1;
    };

    prefetch(0);
    commit(0);
    __syncthreads();

    int buf = 0;
    for (int c = 0; c < NCHUNK; c++) {
        if (c + 1 < NCHUNK) prefetch(c + 1);   // LDG issued early, lands in regs
#pragma unroll
        for (int jj = 0; jj < JC; jj++) {
            unsigned long long wv[8];
            const unsigned long long* wp =
                (const unsigned long long*)(&sW[buf][jj][0]);
#pragma unroll
            for (int q = 0; q < 8; q++) wv[q] = wp[tx + 16 * q];
            float4 x4 = *(const float4*)(&sX[buf][jj][ty << 2]);
            unsigned long long xv[4] = {pack2(x4.x, x4.x), pack2(x4.y, x4.y),
                                        pack2(x4.z, x4.z), pack2(x4.w, x4.w)};
#pragma unroll
            for (int i = 0; i < 4; i++)
#pragma unroll
                for (int q = 0; q < 8; q++) fma2(acc[i][q], xv[i], wv[q]);
        }
        if (c + 1 < NCHUNK) commit(buf ^ 1);   // STS AFTER compute: LDG hidden
        __syncthreads();
        buf ^= 1;
    }

    // bias pairs (adjacent): k = 2*(tx+16q), 2*(tx+16q)+1
    unsigned long long bv[8];
#pragma unroll
    for (int q = 0; q < 8; q++) {
        float2 b2 = *(const float2*)(bias + wcol + 2 * (tx + 16 * q));
        bv[q] = pack2(b2.x, b2.y);
    }

    if (MODE == 0) {
#pragma unroll
        for (int i = 0; i < 4; i++) {
            int b = (ty << 2) + i;
            float xh = g_xT[h * BB + b];
            unsigned long long xh2 = pack2(xh, xh);
            float* dst = g_partQ + (size_t)h * (BB * HH) + b * HH + kb;
#pragma unroll
            for (int q = 0; q < 8; q++) {
                unsigned long long pr = mul2(add2(acc[i][q], bv[q]), xh2);
                float lo, hi;
                unpack2(pr, lo, hi);
                float2 o; o.x = lo; o.y = hi;
                *(float2*)(dst + 2 * (tx + 16 * q)) = o;
            }
        }
    } else {
        double part[4] = {0.0, 0.0, 0.0, 0.0};
#pragma unroll
        for (int i = 0; i < 4; i++) {
            int b = (ty << 2) + i;
            const float* qrow = g_Q + b * HH + kb;
#pragma unroll
            for (int q = 0; q < 8; q++) {
                unsigned long long ct = add2(acc[i][q], bv[q]);
                float lo, hi;
                unpack2(ct, lo, hi);
                float2 q2 = *(const float2*)(qrow + 2 * (tx + 16 * q));
                part[i] += (double)lo * (double)q2.x + (double)hi * (double)q2.y;
            }
        }
#pragma unroll
        for (int i = 0; i < 4; i++) sRed[(ty << 2) + i][tx] = part[i];
        __syncthreads();
        if (tid < BB) {
            double s = 0.0;
#pragma unroll
            for (int t = 0; t < 16; t++) s += sRed[tid][t];  // fixed order
            g_partU[(kh * BB + tid) * HH + h] = (float)s;
        }
    }
}

// ---------------- deterministic reduction of partQ over h ----------------
__global__ void reduceQ_kernel() {
    int idx = blockIdx.x * 256 + threadIdx.x;  // b*512 + k
    double s = 0.0;
#pragma unroll 8
    for (int h = 0; h < HH; h++) s += (double)g_partQ[(size_t)h * (BB * HH) + idx];
    g_Q[idx] = (float)s;
}

// ---------------- compat[b,n] = norm * ( ve[b,n,:] . u[b,:] ) ----------------
__global__ void compat_kernel(const float* __restrict__ ve) {
    int b = blockIdx.y;
    __shared__ float su[HH];
    for (int i = threadIdx.x; i < HH; i += 256)
        su[i] = g_partU[b * HH + i] + g_partU[(BB + b) * HH + i];
    __syncthreads();

    int warp = threadIdx.x >> 5, lane = threadIdx.x & 31;
    for (int r = warp; r < 64; r += 8) {
        int n = blockIdx.x * 64 + r;
        const float4* row = (const float4*)(ve + ((size_t)b * NN + n) * HH);
        const float4* uu = (const float4*)su;
        double s = 0.0;
#pragma unroll
        for (int c4 = lane; c4 < 128; c4 += 32) {
            float4 v = row[c4];
            float4 w = uu[c4];
            s += (double)v.x * w.x + (double)v.y * w.y +
                 (double)v.z * w.z + (double)v.w * w.w;
        }
#pragma unroll
        for (int o = 16; o; o >>= 1) s += __shfl_xor_sync(0xffffffffu, s, o);
        if (lane == 0)
            g_compat[b * NN + n] = __fmul_rn((float)s, NORM_F);  // fp32, as reference
    }
}

// ---------------- reference expf replica: cephes core + FLUSH BELOW FLT_MIN ----
// Validated round 10/11: zero at fx<=-127 AND any result < 2^-126 flushed.
__device__ double exp_ref_f32(float din) {
    float cx = fminf(din, 88.3762626647950f);
    cx = fmaxf(cx, -88.3762626647949f);
    float fx = floorf(__fadd_rn(__fmul_rn(cx, 1.44269504088896341f), 0.5f));
    if (fx <= -127.0f) return 0.0;
    float tmp = __fmul_rn(fx, 0.693359375f);
    float zz  = __fmul_rn(fx, -2.12194440e-4f);
    float x = __fsub_rn(cx, tmp);
    x = __fsub_rn(x, zz);
    float z = __fmul_rn(x, x);
    float y = 1.9875691500e-4f;
    y = __fmaf_rn(y, x, 1.3981999507e-3f);
    y = __fmaf_rn(y, x, 8.3334519073e-3f);
    y = __fmaf_rn(y, x, 4.1665795894e-2f);
    y = __fmaf_rn(y, x, 1.6666665459e-1f);
    y = __fmaf_rn(y, x, 5.0000001201e-1f);
    y = __fmaf_rn(y, z, x);
    y = __fadd_rn(y, 1.0f);
    int n = (int)fx;                        // n in [-126, 127]
    double e = ldexp((double)y, n);         // exact in double
    if (e < 1.1754943508222875e-38) return 0.0;   // subnormal result -> flushed
    return (double)(float)e;                // normal range: exact RN32
}

// ---------------- top-256: fp32 softmax replica + stable argsort ---------------
// Identical semantics to the passing round; restructured so each thread keeps
// its 4 candidate keys in registers and counts in ONE pass over j (4x fewer LDS).
__global__ void __launch_bounds__(512)
topk_kernel() {
    int b = blockIdx.x;
    __shared__ float sv[NN];               // 8 KB
    __shared__ double se[NN];              // 16 KB, reused for keys
    __shared__ float smax[512];            // 2 KB
    __shared__ double ssum[512];           // 4 KB
    int tid = threadIdx.x;

    float lm = -3.0e38f;
    for (int i = tid; i < NN; i += 512) {
        float v = g_compat[b * NN + i];
        sv[i] = v;
        lm = fmaxf(lm, v);
    }
    smax[tid] = lm;
    __syncthreads();
    for (int s = 256; s; s >>= 1) {
        if (tid < s) smax[tid] = fmaxf(smax[tid], smax[tid + s]);
        __syncthreads();
    }
    float m = smax[0];

    double ls = 0.0;
    for (int i = tid; i < NN; i += 512) {
        double e = exp_ref_f32(__fsub_rn(sv[i], m));
        se[i] = e;
        ls += e;
    }
    ssum[tid] = ls;
    __syncthreads();
    for (int s = 256; s; s >>= 1) {
        if (tid < s) ssum[tid] += ssum[tid + s];   // fixed-order: deterministic
        __syncthreads();
    }
    float ssf = (float)ssum[0];

    unsigned long long* keys = (unsigned long long*)se;  // in-place reuse
    for (int i = tid; i < NN; i += 512) {
        double t = se[i] / (double)ssf;
        unsigned u;
        if (t >= 1.1754943508222875e-38) {
            u = __float_as_uint((float)t);                     // normal: exact RN32
        } else {
            u = (unsigned)(long long)nearbyint(t * 0x1p+149);  // subnormal bits / 0
        }
        keys[i] = ((unsigned long long)u << 32) | (unsigned)(NN - 1 - i);
    }
    __syncthreads();

    unsigned long long me[4];
    int cnt[4] = {0, 0, 0, 0};
#pragma unroll
    for (int t = 0; t < 4; t++) me[t] = keys[t * 512 + tid];
#pragma unroll 8
    for (int j = 0; j < NN; j++) {
        unsigned long long kj = keys[j];
#pragma unroll
        for (int t = 0; t < 4; t++) cnt[t] += (kj > me[t]) ? 1 : 0;
    }
#pragma unroll
    for (int t = 0; t < 4; t++)
        if (cnt[t] < NF) g_top[b * NF + cnt[t]] = t * 512 + tid;
}

// ---------------- gather ----------------
__global__ void gather_kernel(const float* __restrict__ ve, float* __restrict__ out) {
    int b = blockIdx.y, r = blockIdx.x;
    int src = g_top[b * NF + r];
    const float4* s = (const float4*)(ve + ((size_t)b * NN + src) * HH);
    float4* d = (float4*)(out + ((size_t)b * NF + r) * HH);
    d[threadIdx.x] = s[threadIdx.x];
}

// ---------------- launch ----------------
extern "C" void kernel_launch(void* const* d_in, const int* in_sizes, int n_in,
                              void* d_out, int out_size) {
    // Identify inputs by element count (robust, keeps relative order of pairs):
    // vs=32768, ve=67108864, Wq/Wk=134217728, bq/bk=262144.
    const float* vs = nullptr;
    const float* ve = nullptr;
    const float* Wq = nullptr;
    const float* Wk = nullptr;
    const float* bq = nullptr;
    const float* bk = nullptr;
    int nW = 0, nB = 0;
    for (int i = 0; i < n_in; i++) {
        const float* p = (const float*)d_in[i];
        int s = in_sizes[i];
        if (s == 32768) vs = p;
        else if (s == 67108864) ve = p;
        else if (s == 134217728) { if (nW++ == 0) Wq = p; else Wk = p; }
        else if (s == 262144)    { if (nB++ == 0) bq = p; else bk = p; }
    }
    float* out = (float*)d_out;

    prep_kernel<<<128, 256>>>(vs);
    gen_kernel<0><<<dim3(HH, 2), 256>>>(Wq, bq);
    reduceQ_kernel<<<128, 256>>>();
    gen_kernel<1><<<dim3(HH, 2), 256>>>(Wk, bk);
    compat_kernel<<<dim3(32, BB), 256>>>(ve);
    topk_kernel<<<BB, 512>>>();
    gather_kernel<<<dim3(NF, BB), 128>>>(ve, out);
}